// round 1
// baseline (speedup 1.0000x reference)
#include <cuda_runtime.h>

#define TF 8        // node features
#define TE 32       // embed dim (output cols)
#define TH 64       // hidden dim
#define TILE 128    // nodes per tile
#define NTHREADS 256

// Shared memory layout (in floats):
//   Ws1 [40][64]   @ 0      (2560)
//   Ws2 [64][64]   @ 2560   (4096)
//   Ws3 [64][32]   @ 6656   (2048)
//   Bs1 [64]       @ 8704
//   Bs2 [64]       @ 8768
//   Bs3 [32]       @ 8832   (pad to 8864)
//   As  [40][132]  @ 8864   (5280)  transposed input tile (stride 132, 16B-aligned rows)
//   H1s [128][65]  @ 14144  (8320)  hidden1; reused as final [128][32+] output buffer
//   H2s [128][65]  @ 22464  (8320)  hidden2
// total 30784 floats = 123136 bytes
#define SMEM_FLOATS 30784

__global__ void zero_out_kernel(float* __restrict__ out, int n) {
    int i = blockIdx.x * blockDim.x + threadIdx.x;
    if (i < n) out[i] = 0.0f;
}

__global__ __launch_bounds__(NTHREADS, 1)
void dag_encoder_kernel(
    const float* __restrict__ x, const float* __restrict__ h_node,
    const float* __restrict__ W1, const float* __restrict__ b1,
    const float* __restrict__ W2, const float* __restrict__ b2,
    const float* __restrict__ W3, const float* __restrict__ b3,
    const int*   __restrict__ ptr, float* __restrict__ out,
    int N, int M)
{
    extern __shared__ float smem[];
    float* Ws1 = smem;
    float* Ws2 = smem + 2560;
    float* Ws3 = smem + 6656;
    float* Bs1 = smem + 8704;
    float* Bs2 = smem + 8768;
    float* Bs3 = smem + 8832;
    float* As  = smem + 8864;
    float* H1s = smem + 14144;
    float* H2s = smem + 22464;
    __shared__ int s_seg[TILE];

    const int t = threadIdx.x;

    // Stage weights + biases once per (persistent) CTA
    for (int i = t; i < (TF + TE) * TH; i += NTHREADS) Ws1[i] = W1[i];
    for (int i = t; i < TH * TH;        i += NTHREADS) Ws2[i] = W2[i];
    for (int i = t; i < TH * TE;        i += NTHREADS) Ws3[i] = W3[i];
    if (t < TH) { Bs1[t] = b1[t]; Bs2[t] = b2[t]; }
    else if (t >= 128 && t < 128 + TE) Bs3[t - 128] = b3[t - 128];
    __syncthreads();

    const int row = t >> 4;        // 0..15 -> m block
    const int colc = t & 15;       // 0..15 -> n block
    const int m0 = row * 8;        // 8 rows per thread
    const int n0 = colc * 4;       // 4 cols per thread (layers 1,2)

    const int numTiles = (N + TILE - 1) / TILE;
    for (int tile = blockIdx.x; tile < numTiles; tile += gridDim.x) {
        const int base = tile * TILE;

        // ---- load input tile, transposed into As[k][m] (stride 132) ----
        for (int i = t; i < TILE * TF; i += NTHREADS) {
            int m = i >> 3, k = i & 7;
            int node = base + m;
            As[k * 132 + m] = (node < N) ? x[node * TF + k] : 0.0f;
        }
        for (int i = t; i < TILE * TE; i += NTHREADS) {
            int m = i >> 5, e = i & 31;
            int node = base + m;
            As[(TF + e) * 132 + m] = (node < N) ? h_node[node * TE + e] : 0.0f;
        }
        // ---- segment id per node: upper_bound(ptr, node) - 1 ----
        if (t < TILE) {
            int node = base + t;
            int s = -1;
            if (node < N) {
                int lo = 0, hi = M + 1;
                while (lo < hi) {
                    int mid = (lo + hi) >> 1;
                    if (ptr[mid] <= node) lo = mid + 1; else hi = mid;
                }
                s = lo - 1;
            }
            s_seg[t] = s;
        }
        __syncthreads();

        // ---- Layer 1: H1 = relu(A @ W1 + b1), A is [128][40] ----
        {
            float acc[8][4];
            #pragma unroll
            for (int i = 0; i < 8; i++)
                #pragma unroll
                for (int j = 0; j < 4; j++) acc[i][j] = 0.0f;

            #pragma unroll 4
            for (int k = 0; k < TF + TE; k++) {
                const float4 a0 = *(const float4*)(As + k * 132 + m0);
                const float4 a1 = *(const float4*)(As + k * 132 + m0 + 4);
                const float4 bv = *(const float4*)(Ws1 + k * TH + n0);
                float a[8] = {a0.x, a0.y, a0.z, a0.w, a1.x, a1.y, a1.z, a1.w};
                float b[4] = {bv.x, bv.y, bv.z, bv.w};
                #pragma unroll
                for (int i = 0; i < 8; i++)
                    #pragma unroll
                    for (int j = 0; j < 4; j++)
                        acc[i][j] = fmaf(a[i], b[j], acc[i][j]);
            }
            float bb[4];
            #pragma unroll
            for (int j = 0; j < 4; j++) bb[j] = Bs1[n0 + j];
            #pragma unroll
            for (int i = 0; i < 8; i++)
                #pragma unroll
                for (int j = 0; j < 4; j++)
                    H1s[(m0 + i) * 65 + n0 + j] = fmaxf(acc[i][j] + bb[j], 0.0f);
        }
        __syncthreads();

        // ---- Layer 2: H2 = relu(H1 @ W2 + b2) ----
        {
            float acc[8][4];
            #pragma unroll
            for (int i = 0; i < 8; i++)
                #pragma unroll
                for (int j = 0; j < 4; j++) acc[i][j] = 0.0f;

            #pragma unroll 4
            for (int k = 0; k < TH; k++) {
                float a[8];
                #pragma unroll
                for (int i = 0; i < 8; i++) a[i] = H1s[(m0 + i) * 65 + k];  // broadcast across lanes
                const float4 bv = *(const float4*)(Ws2 + k * TH + n0);
                float b[4] = {bv.x, bv.y, bv.z, bv.w};
                #pragma unroll
                for (int i = 0; i < 8; i++)
                    #pragma unroll
                    for (int j = 0; j < 4; j++)
                        acc[i][j] = fmaf(a[i], b[j], acc[i][j]);
            }
            float bb[4];
            #pragma unroll
            for (int j = 0; j < 4; j++) bb[j] = Bs2[n0 + j];
            #pragma unroll
            for (int i = 0; i < 8; i++)
                #pragma unroll
                for (int j = 0; j < 4; j++)
                    H2s[(m0 + i) * 65 + n0 + j] = fmaxf(acc[i][j] + bb[j], 0.0f);
        }
        __syncthreads();

        // ---- Layer 3: C3 = H2 @ W3 + b3  (write into H1s buffer) ----
        {
            const int n0c = colc * 2;   // 16 * 2 = 32 output cols
            float acc[8][2];
            #pragma unroll
            for (int i = 0; i < 8; i++) { acc[i][0] = 0.0f; acc[i][1] = 0.0f; }

            #pragma unroll 4
            for (int k = 0; k < TH; k++) {
                float a[8];
                #pragma unroll
                for (int i = 0; i < 8; i++) a[i] = H2s[(m0 + i) * 65 + k];
                const float2 bv = *(const float2*)(Ws3 + k * TE + n0c);
                #pragma unroll
                for (int i = 0; i < 8; i++) {
                    acc[i][0] = fmaf(a[i], bv.x, acc[i][0]);
                    acc[i][1] = fmaf(a[i], bv.y, acc[i][1]);
                }
            }
            const float bb0 = Bs3[n0c], bb1 = Bs3[n0c + 1];
            #pragma unroll
            for (int i = 0; i < 8; i++) {
                H1s[(m0 + i) * 65 + n0c]     = acc[i][0] + bb0;
                H1s[(m0 + i) * 65 + n0c + 1] = acc[i][1] + bb1;
            }
        }
        __syncthreads();

        // ---- Segment flush: run-length reduce within tile, atomicAdd per run ----
        // 128 threads: col = t&31 (output column), q = t>>5 (32-node chunk).
        if (t < 128) {
            const int c = t & 31;
            const int q = t >> 5;
            int cur = -1;
            float acc = 0.0f;
            #pragma unroll 4
            for (int i = 0; i < 32; i++) {
                int m = q * 32 + i;
                int s = s_seg[m];
                if (s < 0) break;                   // past end of N (tail tile)
                float v = H1s[m * 65 + c];
                if (s != cur) {
                    if (cur >= 0) atomicAdd(&out[cur * TE + c], acc);
                    cur = s; acc = v;
                } else {
                    acc += v;
                }
            }
            if (cur >= 0) atomicAdd(&out[cur * TE + c], acc);
        }
        __syncthreads();   // protect s_seg / H1s before next tile
    }
}

extern "C" void kernel_launch(void* const* d_in, const int* in_sizes, int n_in,
                              void* d_out, int out_size) {
    const float* x      = (const float*)d_in[0];
    const float* h_node = (const float*)d_in[1];
    const float* W1     = (const float*)d_in[2];
    const float* b1     = (const float*)d_in[3];
    const float* W2     = (const float*)d_in[4];
    const float* b2     = (const float*)d_in[5];
    const float* W3     = (const float*)d_in[6];
    const float* b3     = (const float*)d_in[7];
    const int*   ptr    = (const int*)d_in[8];
    float* out = (float*)d_out;

    const int N = in_sizes[1] / TE;      // h_node is [N, 32]
    const int M = in_sizes[8] - 1;       // ptr has M+1 entries

    // zero-init output (harness poisons it; empty segments must be 0)
    zero_out_kernel<<<(out_size + 255) / 256, 256>>>(out, out_size);

    const int smem_bytes = SMEM_FLOATS * (int)sizeof(float);
    cudaFuncSetAttribute(dag_encoder_kernel,
                         cudaFuncAttributeMaxDynamicSharedMemorySize, smem_bytes);

    int dev = 0;
    cudaGetDevice(&dev);
    int sm_count = 148;
    cudaDeviceGetAttribute(&sm_count, cudaDevAttrMultiProcessorCount, dev);

    dag_encoder_kernel<<<sm_count, NTHREADS, smem_bytes>>>(
        x, h_node, W1, b1, W2, b2, W3, b3, ptr, out, N, M);
}

// round 3
// speedup vs baseline: 4.6089x; 4.6089x over previous
#include <cuda_runtime.h>
#include <cuda_bf16.h>
#include <cstdint>

#define NT 128
#define CHUNK 32

// segment id per node, precomputed (8 MB __device__ scratch — allowed)
__device__ int g_seg[2000128];

// ---------------- shared memory byte offsets ----------------
#define OFF_W1HI 0        // [64 n][56 kp] bf16 (k<48 valid)  7168 B
#define OFF_W1LO 7168
#define OFF_W2HI 14336    // [64 n][72 kp] bf16 (k<64 valid)  9216 B
#define OFF_W2LO 23552
#define OFF_W3HI 32768    // [32 n][72 kp] bf16               4608 B
#define OFF_W3LO 37376
#define OFF_B1   41984    // 64 f32
#define OFF_B2   42240    // 64 f32
#define OFF_B3   42496    // 32 f32
#define OFF_FLUSH 42624   // 4 warps * 32*33 f32 = 16896 B
#define SMEM_BYTES 59520

static __device__ __forceinline__ void mma_bf16(float c[4], const uint32_t a[4],
                                                uint32_t b0, uint32_t b1) {
    asm volatile(
        "mma.sync.aligned.m16n8k16.row.col.f32.bf16.bf16.f32 "
        "{%0,%1,%2,%3}, {%4,%5,%6,%7}, {%8,%9}, {%0,%1,%2,%3};"
        : "+f"(c[0]), "+f"(c[1]), "+f"(c[2]), "+f"(c[3])
        : "r"(a[0]), "r"(a[1]), "r"(a[2]), "r"(a[3]), "r"(b0), "r"(b1));
}

// pack two fp32 into bf16x2 by TRUNCATION (upper 16 bits) — 1 instr
static __device__ __forceinline__ uint32_t pack_hi(float v0, float v1) {
    return __byte_perm(__float_as_uint(v0), __float_as_uint(v1), 0x7632);
}
// residual lo = v - trunc(v), packed round-to-nearest
static __device__ __forceinline__ uint32_t pack_lo(float v0, float v1) {
    float h0 = __uint_as_float(__float_as_uint(v0) & 0xFFFF0000u);
    float h1 = __uint_as_float(__float_as_uint(v1) & 0xFFFF0000u);
    __nv_bfloat162 p = __floats2bfloat162_rn(v0 - h0, v1 - h1);
    return *(uint32_t*)&p;
}

__global__ void zero_out_kernel(float* __restrict__ out, int n) {
    int i = blockIdx.x * blockDim.x + threadIdx.x;
    if (i < n) out[i] = 0.0f;
}

__global__ void segfill_kernel(const int* __restrict__ ptr, int M) {
    int s = blockIdx.x;
    if (s >= M) return;
    int a = ptr[s], b = ptr[s + 1];
    for (int i = a + threadIdx.x; i < b; i += blockDim.x) g_seg[i] = s;
}

__global__ __launch_bounds__(NT, 2)
void dag_mma_kernel(
    const float* __restrict__ x, const float* __restrict__ h_node,
    const float* __restrict__ W1, const float* __restrict__ b1,
    const float* __restrict__ W2, const float* __restrict__ b2,
    const float* __restrict__ W3, const float* __restrict__ b3,
    float* __restrict__ out, int N, int numChunks)
{
    extern __shared__ char smem[];

    const int t = threadIdx.x;

    // ---- stage weights into shared as [n][k] bf16, truncation hi + residual lo ----
    for (int i = t; i < 64 * 48; i += NT) {                  // W1: k padded 40->48
        int n = i / 48, k = i % 48;
        float w = (k < 40) ? W1[k * 64 + n] : 0.0f;
        uint32_t u = __float_as_uint(w);
        *(uint16_t*)(smem + OFF_W1HI + (n * 56 + k) * 2) = (uint16_t)(u >> 16);
        float l = w - __uint_as_float(u & 0xFFFF0000u);
        *(__nv_bfloat16*)(smem + OFF_W1LO + (n * 56 + k) * 2) = __float2bfloat16(l);
    }
    for (int i = t; i < 64 * 64; i += NT) {                  // W2
        int n = i / 64, k = i % 64;
        float w = W2[k * 64 + n];
        uint32_t u = __float_as_uint(w);
        *(uint16_t*)(smem + OFF_W2HI + (n * 72 + k) * 2) = (uint16_t)(u >> 16);
        float l = w - __uint_as_float(u & 0xFFFF0000u);
        *(__nv_bfloat16*)(smem + OFF_W2LO + (n * 72 + k) * 2) = __float2bfloat16(l);
    }
    for (int i = t; i < 32 * 64; i += NT) {                  // W3
        int n = i / 64, k = i % 64;
        float w = W3[k * 32 + n];
        uint32_t u = __float_as_uint(w);
        *(uint16_t*)(smem + OFF_W3HI + (n * 72 + k) * 2) = (uint16_t)(u >> 16);
        float l = w - __uint_as_float(u & 0xFFFF0000u);
        *(__nv_bfloat16*)(smem + OFF_W3LO + (n * 72 + k) * 2) = __float2bfloat16(l);
    }
    if (t < 64) {
        ((float*)(smem + OFF_B1))[t] = b1[t];
        ((float*)(smem + OFF_B2))[t] = b2[t];
    }
    if (t < 32) ((float*)(smem + OFF_B3))[t] = b3[t];
    __syncthreads();

    const float* b1s = (const float*)(smem + OFF_B1);
    const float* b2s = (const float*)(smem + OFF_B2);
    const float* b3s = (const float*)(smem + OFF_B3);

    const int lane = t & 31;
    const int wid  = t >> 5;
    const int i4 = lane & 3;    // t%4 -> column pair selector
    const int r4 = lane >> 2;   // t/4 -> row selector
    float* fbuf = (float*)(smem + OFF_FLUSH) + wid * (32 * 33);

    const int warpsTotal = gridDim.x * (NT / 32);
    const int warpGlobal = blockIdx.x * (NT / 32) + wid;

    for (int c = warpGlobal; c < numChunks; c += warpsTotal) {
        const int base = c * CHUNK;

        // segment id of this lane's row
        int myseg = -1;
        { int node = base + lane; if (node < N) myseg = g_seg[node]; }

        // ================= Layer 1: [32 x 40] @ [40 x 64] =================
        float acc1[2][8][4];
        #pragma unroll
        for (int mt = 0; mt < 2; mt++)
            #pragma unroll
            for (int nt = 0; nt < 8; nt++)
                #pragma unroll
                for (int q = 0; q < 4; q++) acc1[mt][nt][q] = 0.0f;

        #pragma unroll
        for (int kt = 0; kt < 3; kt++) {
            uint32_t ah[2][4], al[2][4];
            #pragma unroll
            for (int mt = 0; mt < 2; mt++) {
                const int rA = base + mt * 16 + r4;
                const int rB = rA + 8;
                #pragma unroll
                for (int p = 0; p < 2; p++) {
                    const int kk = kt * 16 + 2 * i4 + 8 * p;
                    float2 fA = make_float2(0.f, 0.f), fB = make_float2(0.f, 0.f);
                    if (kk < 8) {
                        if (rA < N) fA = *(const float2*)(x + (size_t)rA * 8 + kk);
                        if (rB < N) fB = *(const float2*)(x + (size_t)rB * 8 + kk);
                    } else if (kk < 40) {
                        if (rA < N) fA = *(const float2*)(h_node + (size_t)rA * 32 + (kk - 8));
                        if (rB < N) fB = *(const float2*)(h_node + (size_t)rB * 32 + (kk - 8));
                    }
                    ah[mt][2 * p]     = pack_hi(fA.x, fA.y);
                    ah[mt][2 * p + 1] = pack_hi(fB.x, fB.y);
                    al[mt][2 * p]     = pack_lo(fA.x, fA.y);
                    al[mt][2 * p + 1] = pack_lo(fB.x, fB.y);
                }
            }
            #pragma unroll
            for (int nt = 0; nt < 8; nt++) {
                const int off = ((nt * 8 + r4) * 56 + kt * 16 + 2 * i4) * 2;
                uint32_t bh0 = *(const uint32_t*)(smem + OFF_W1HI + off);
                uint32_t bh1 = *(const uint32_t*)(smem + OFF_W1HI + off + 16);
                uint32_t bl0 = *(const uint32_t*)(smem + OFF_W1LO + off);
                uint32_t bl1 = *(const uint32_t*)(smem + OFF_W1LO + off + 16);
                #pragma unroll
                for (int mt = 0; mt < 2; mt++) {
                    mma_bf16(acc1[mt][nt], ah[mt], bh0, bh1);
                    mma_bf16(acc1[mt][nt], ah[mt], bl0, bl1);
                    mma_bf16(acc1[mt][nt], al[mt], bh0, bh1);
                }
            }
        }
        // epi1: bias + relu (acc layout cols: 2*i4, 2*i4+1 within n-tile)
        #pragma unroll
        for (int nt = 0; nt < 8; nt++) {
            float2 bb = *(const float2*)(b1s + nt * 8 + 2 * i4);
            #pragma unroll
            for (int mt = 0; mt < 2; mt++) {
                acc1[mt][nt][0] = fmaxf(acc1[mt][nt][0] + bb.x, 0.0f);
                acc1[mt][nt][1] = fmaxf(acc1[mt][nt][1] + bb.y, 0.0f);
                acc1[mt][nt][2] = fmaxf(acc1[mt][nt][2] + bb.x, 0.0f);
                acc1[mt][nt][3] = fmaxf(acc1[mt][nt][3] + bb.y, 0.0f);
            }
        }

        // ================= Layer 2: [32 x 64] @ [64 x 64] =================
        float acc2[2][8][4];
        #pragma unroll
        for (int mt = 0; mt < 2; mt++)
            #pragma unroll
            for (int nt = 0; nt < 8; nt++)
                #pragma unroll
                for (int q = 0; q < 4; q++) acc2[mt][nt][q] = 0.0f;

        #pragma unroll
        for (int kt = 0; kt < 4; kt++) {
            uint32_t ah[2][4], al[2][4];
            #pragma unroll
            for (int mt = 0; mt < 2; mt++) {
                const float* s0 = acc1[mt][2 * kt];
                const float* s1 = acc1[mt][2 * kt + 1];
                ah[mt][0] = pack_hi(s0[0], s0[1]);  al[mt][0] = pack_lo(s0[0], s0[1]);
                ah[mt][1] = pack_hi(s0[2], s0[3]);  al[mt][1] = pack_lo(s0[2], s0[3]);
                ah[mt][2] = pack_hi(s1[0], s1[1]);  al[mt][2] = pack_lo(s1[0], s1[1]);
                ah[mt][3] = pack_hi(s1[2], s1[3]);  al[mt][3] = pack_lo(s1[2], s1[3]);
            }
            #pragma unroll
            for (int nt = 0; nt < 8; nt++) {
                const int off = ((nt * 8 + r4) * 72 + kt * 16 + 2 * i4) * 2;
                uint32_t bh0 = *(const uint32_t*)(smem + OFF_W2HI + off);
                uint32_t bh1 = *(const uint32_t*)(smem + OFF_W2HI + off + 16);
                uint32_t bl0 = *(const uint32_t*)(smem + OFF_W2LO + off);
                uint32_t bl1 = *(const uint32_t*)(smem + OFF_W2LO + off + 16);
                #pragma unroll
                for (int mt = 0; mt < 2; mt++) {
                    mma_bf16(acc2[mt][nt], ah[mt], bh0, bh1);
                    mma_bf16(acc2[mt][nt], ah[mt], bl0, bl1);
                    mma_bf16(acc2[mt][nt], al[mt], bh0, bh1);
                }
            }
        }
        // epi2
        #pragma unroll
        for (int nt = 0; nt < 8; nt++) {
            float2 bb = *(const float2*)(b2s + nt * 8 + 2 * i4);
            #pragma unroll
            for (int mt = 0; mt < 2; mt++) {
                acc2[mt][nt][0] = fmaxf(acc2[mt][nt][0] + bb.x, 0.0f);
                acc2[mt][nt][1] = fmaxf(acc2[mt][nt][1] + bb.y, 0.0f);
                acc2[mt][nt][2] = fmaxf(acc2[mt][nt][2] + bb.x, 0.0f);
                acc2[mt][nt][3] = fmaxf(acc2[mt][nt][3] + bb.y, 0.0f);
            }
        }

        // ================= Layer 3: [32 x 64] @ [64 x 32] =================
        float acc3[2][4][4];
        #pragma unroll
        for (int mt = 0; mt < 2; mt++)
            #pragma unroll
            for (int nt = 0; nt < 4; nt++)
                #pragma unroll
                for (int q = 0; q < 4; q++) acc3[mt][nt][q] = 0.0f;

        #pragma unroll
        for (int kt = 0; kt < 4; kt++) {
            uint32_t ah[2][4], al[2][4];
            #pragma unroll
            for (int mt = 0; mt < 2; mt++) {
                const float* s0 = acc2[mt][2 * kt];
                const float* s1 = acc2[mt][2 * kt + 1];
                ah[mt][0] = pack_hi(s0[0], s0[1]);  al[mt][0] = pack_lo(s0[0], s0[1]);
                ah[mt][1] = pack_hi(s0[2], s0[3]);  al[mt][1] = pack_lo(s0[2], s0[3]);
                ah[mt][2] = pack_hi(s1[0], s1[1]);  al[mt][2] = pack_lo(s1[0], s1[1]);
                ah[mt][3] = pack_hi(s1[2], s1[3]);  al[mt][3] = pack_lo(s1[2], s1[3]);
            }
            #pragma unroll
            for (int nt = 0; nt < 4; nt++) {
                const int off = ((nt * 8 + r4) * 72 + kt * 16 + 2 * i4) * 2;
                uint32_t bh0 = *(const uint32_t*)(smem + OFF_W3HI + off);
                uint32_t bh1 = *(const uint32_t*)(smem + OFF_W3HI + off + 16);
                uint32_t bl0 = *(const uint32_t*)(smem + OFF_W3LO + off);
                uint32_t bl1 = *(const uint32_t*)(smem + OFF_W3LO + off + 16);
                #pragma unroll
                for (int mt = 0; mt < 2; mt++) {
                    mma_bf16(acc3[mt][nt], ah[mt], bh0, bh1);
                    mma_bf16(acc3[mt][nt], ah[mt], bl0, bl1);
                    mma_bf16(acc3[mt][nt], al[mt], bh0, bh1);
                }
            }
        }

        // epi3: bias, write to per-warp flush buffer [32][33]
        #pragma unroll
        for (int nt = 0; nt < 4; nt++) {
            float2 bb = *(const float2*)(b3s + nt * 8 + 2 * i4);
            #pragma unroll
            for (int mt = 0; mt < 2; mt++) {
                const int rA = mt * 16 + r4;
                const int cc = nt * 8 + 2 * i4;
                fbuf[rA * 33 + cc]           = acc3[mt][nt][0] + bb.x;
                fbuf[rA * 33 + cc + 1]       = acc3[mt][nt][1] + bb.y;
                fbuf[(rA + 8) * 33 + cc]     = acc3[mt][nt][2] + bb.x;
                fbuf[(rA + 8) * 33 + cc + 1] = acc3[mt][nt][3] + bb.y;
            }
        }
        __syncwarp();

        // run-length segment flush: lane owns column `lane`
        {
            int cur = -1;
            float a = 0.0f;
            #pragma unroll 4
            for (int i = 0; i < 32; i++) {
                int s = __shfl_sync(0xffffffffu, myseg, i);
                float v = fbuf[i * 33 + lane];
                if (s != cur) {
                    if (cur >= 0) atomicAdd(&out[cur * 32 + lane], a);
                    cur = s; a = v;
                } else {
                    a += v;
                }
            }
            if (cur >= 0) atomicAdd(&out[cur * 32 + lane], a);
        }
        __syncwarp();
    }
}

extern "C" void kernel_launch(void* const* d_in, const int* in_sizes, int n_in,
                              void* d_out, int out_size) {
    const float* x      = (const float*)d_in[0];
    const float* h_node = (const float*)d_in[1];
    const float* W1     = (const float*)d_in[2];
    const float* b1     = (const float*)d_in[3];
    const float* W2     = (const float*)d_in[4];
    const float* b2     = (const float*)d_in[5];
    const float* W3     = (const float*)d_in[6];
    const float* b3     = (const float*)d_in[7];
    const int*   ptr    = (const int*)d_in[8];
    float* out = (float*)d_out;

    const int N = in_sizes[1] / 32;     // h_node is [N, 32]
    const int M = in_sizes[8] - 1;      // ptr has M+1 entries
    const int numChunks = (N + CHUNK - 1) / CHUNK;

    zero_out_kernel<<<(out_size + 255) / 256, 256>>>(out, out_size);
    segfill_kernel<<<M, 64>>>(ptr, M);

    cudaFuncSetAttribute(dag_mma_kernel,
                         cudaFuncAttributeMaxDynamicSharedMemorySize, SMEM_BYTES);

    int dev = 0;
    cudaGetDevice(&dev);
    int sm_count = 148;
    cudaDeviceGetAttribute(&sm_count, cudaDevAttrMultiProcessorCount, dev);

    dag_mma_kernel<<<sm_count * 2, NT, SMEM_BYTES>>>(
        x, h_node, W1, b1, W2, b2, W3, b3, out, N, numChunks);
}

// round 4
// speedup vs baseline: 4.6151x; 1.0014x over previous
#include <cuda_runtime.h>
#include <cuda_bf16.h>
#include <cstdint>

#define NT 128
#define CHUNK 32

// segment id per node, precomputed (8 MB __device__ scratch — allowed)
__device__ int g_seg[2000128];

// ---------------- shared memory byte offsets ----------------
#define OFF_W1HI 0        // [64 n][56 kp] bf16 (k<48 valid)  7168 B
#define OFF_W1LO 7168
#define OFF_W2HI 14336    // [64 n][72 kp] bf16 (k<64 valid)  9216 B
#define OFF_W2LO 23552
#define OFF_W3HI 32768    // [32 n][72 kp] bf16               4608 B
#define OFF_W3LO 37376
#define OFF_B1   41984    // 64 f32
#define OFF_B2   42240    // 64 f32
#define OFF_B3   42496    // 32 f32
#define OFF_FLUSH 42624   // 4 warps * 32*33 f32 = 16896 B
#define SMEM_BYTES 59520

static __device__ __forceinline__ void mma_bf16(float c[4], const uint32_t a[4],
                                                uint32_t b0, uint32_t b1) {
    asm volatile(
        "mma.sync.aligned.m16n8k16.row.col.f32.bf16.bf16.f32 "
        "{%0,%1,%2,%3}, {%4,%5,%6,%7}, {%8,%9}, {%0,%1,%2,%3};"
        : "+f"(c[0]), "+f"(c[1]), "+f"(c[2]), "+f"(c[3])
        : "r"(a[0]), "r"(a[1]), "r"(a[2]), "r"(a[3]), "r"(b0), "r"(b1));
}

// pack two fp32 into bf16x2 by TRUNCATION (upper 16 bits) — 1 instr
static __device__ __forceinline__ uint32_t pack_hi(float v0, float v1) {
    return __byte_perm(__float_as_uint(v0), __float_as_uint(v1), 0x7632);
}
// residual lo = v - trunc(v), packed round-to-nearest
static __device__ __forceinline__ uint32_t pack_lo(float v0, float v1) {
    float h0 = __uint_as_float(__float_as_uint(v0) & 0xFFFF0000u);
    float h1 = __uint_as_float(__float_as_uint(v1) & 0xFFFF0000u);
    __nv_bfloat162 p = __floats2bfloat162_rn(v0 - h0, v1 - h1);
    return *(uint32_t*)&p;
}

__global__ void zero_out_kernel(float* __restrict__ out, int n) {
    int i = blockIdx.x * blockDim.x + threadIdx.x;
    if (i < n) out[i] = 0.0f;
}

__global__ void segfill_kernel(const int* __restrict__ ptr, int M) {
    int s = blockIdx.x;
    if (s >= M) return;
    int a = ptr[s], b = ptr[s + 1];
    for (int i = a + threadIdx.x; i < b; i += blockDim.x) g_seg[i] = s;
}

__global__ __launch_bounds__(NT, 2)
void dag_mma_kernel(
    const float* __restrict__ x, const float* __restrict__ h_node,
    const float* __restrict__ W1, const float* __restrict__ b1,
    const float* __restrict__ W2, const float* __restrict__ b2,
    const float* __restrict__ W3, const float* __restrict__ b3,
    float* __restrict__ out, int N, int numChunks)
{
    extern __shared__ char smem[];

    const int t = threadIdx.x;

    // ---- stage weights into shared as [n][k] bf16, truncation hi + residual lo ----
    for (int i = t; i < 64 * 48; i += NT) {                  // W1: k padded 40->48
        int n = i / 48, k = i % 48;
        float w = (k < 40) ? W1[k * 64 + n] : 0.0f;
        uint32_t u = __float_as_uint(w);
        *(uint16_t*)(smem + OFF_W1HI + (n * 56 + k) * 2) = (uint16_t)(u >> 16);
        float l = w - __uint_as_float(u & 0xFFFF0000u);
        *(__nv_bfloat16*)(smem + OFF_W1LO + (n * 56 + k) * 2) = __float2bfloat16(l);
    }
    for (int i = t; i < 64 * 64; i += NT) {                  // W2
        int n = i / 64, k = i % 64;
        float w = W2[k * 64 + n];
        uint32_t u = __float_as_uint(w);
        *(uint16_t*)(smem + OFF_W2HI + (n * 72 + k) * 2) = (uint16_t)(u >> 16);
        float l = w - __uint_as_float(u & 0xFFFF0000u);
        *(__nv_bfloat16*)(smem + OFF_W2LO + (n * 72 + k) * 2) = __float2bfloat16(l);
    }
    for (int i = t; i < 32 * 64; i += NT) {                  // W3
        int n = i / 64, k = i % 64;
        float w = W3[k * 32 + n];
        uint32_t u = __float_as_uint(w);
        *(uint16_t*)(smem + OFF_W3HI + (n * 72 + k) * 2) = (uint16_t)(u >> 16);
        float l = w - __uint_as_float(u & 0xFFFF0000u);
        *(__nv_bfloat16*)(smem + OFF_W3LO + (n * 72 + k) * 2) = __float2bfloat16(l);
    }
    if (t < 64) {
        ((float*)(smem + OFF_B1))[t] = b1[t];
        ((float*)(smem + OFF_B2))[t] = b2[t];
    }
    if (t < 32) ((float*)(smem + OFF_B3))[t] = b3[t];
    __syncthreads();

    const float* b1s = (const float*)(smem + OFF_B1);
    const float* b2s = (const float*)(smem + OFF_B2);
    const float* b3s = (const float*)(smem + OFF_B3);

    const int lane = t & 31;
    const int wid  = t >> 5;
    const int i4 = lane & 3;    // t%4 -> column pair selector
    const int r4 = lane >> 2;   // t/4 -> row selector
    float* fbuf = (float*)(smem + OFF_FLUSH) + wid * (32 * 33);

    const int warpsTotal = gridDim.x * (NT / 32);
    const int warpGlobal = blockIdx.x * (NT / 32) + wid;

    for (int c = warpGlobal; c < numChunks; c += warpsTotal) {
        const int base = c * CHUNK;

        // segment id of this lane's row
        int myseg = -1;
        { int node = base + lane; if (node < N) myseg = g_seg[node]; }

        // ================= Layer 1: [32 x 40] @ [40 x 64] =================
        float acc1[2][8][4];
        #pragma unroll
        for (int mt = 0; mt < 2; mt++)
            #pragma unroll
            for (int nt = 0; nt < 8; nt++)
                #pragma unroll
                for (int q = 0; q < 4; q++) acc1[mt][nt][q] = 0.0f;

        #pragma unroll
        for (int kt = 0; kt < 3; kt++) {
            uint32_t ah[2][4], al[2][4];
            #pragma unroll
            for (int mt = 0; mt < 2; mt++) {
                const int rA = base + mt * 16 + r4;
                const int rB = rA + 8;
                #pragma unroll
                for (int p = 0; p < 2; p++) {
                    const int kk = kt * 16 + 2 * i4 + 8 * p;
                    float2 fA = make_float2(0.f, 0.f), fB = make_float2(0.f, 0.f);
                    if (kk < 8) {
                        if (rA < N) fA = *(const float2*)(x + (size_t)rA * 8 + kk);
                        if (rB < N) fB = *(const float2*)(x + (size_t)rB * 8 + kk);
                    } else if (kk < 40) {
                        if (rA < N) fA = *(const float2*)(h_node + (size_t)rA * 32 + (kk - 8));
                        if (rB < N) fB = *(const float2*)(h_node + (size_t)rB * 32 + (kk - 8));
                    }
                    ah[mt][2 * p]     = pack_hi(fA.x, fA.y);
                    ah[mt][2 * p + 1] = pack_hi(fB.x, fB.y);
                    al[mt][2 * p]     = pack_lo(fA.x, fA.y);
                    al[mt][2 * p + 1] = pack_lo(fB.x, fB.y);
                }
            }
            #pragma unroll
            for (int nt = 0; nt < 8; nt++) {
                const int off = ((nt * 8 + r4) * 56 + kt * 16 + 2 * i4) * 2;
                uint32_t bh0 = *(const uint32_t*)(smem + OFF_W1HI + off);
                uint32_t bh1 = *(const uint32_t*)(smem + OFF_W1HI + off + 16);
                uint32_t bl0 = *(const uint32_t*)(smem + OFF_W1LO + off);
                uint32_t bl1 = *(const uint32_t*)(smem + OFF_W1LO + off + 16);
                #pragma unroll
                for (int mt = 0; mt < 2; mt++) {
                    mma_bf16(acc1[mt][nt], ah[mt], bh0, bh1);
                    mma_bf16(acc1[mt][nt], ah[mt], bl0, bl1);
                    mma_bf16(acc1[mt][nt], al[mt], bh0, bh1);
                }
            }
        }
        // epi1: bias + relu (acc layout cols: 2*i4, 2*i4+1 within n-tile)
        #pragma unroll
        for (int nt = 0; nt < 8; nt++) {
            float2 bb = *(const float2*)(b1s + nt * 8 + 2 * i4);
            #pragma unroll
            for (int mt = 0; mt < 2; mt++) {
                acc1[mt][nt][0] = fmaxf(acc1[mt][nt][0] + bb.x, 0.0f);
                acc1[mt][nt][1] = fmaxf(acc1[mt][nt][1] + bb.y, 0.0f);
                acc1[mt][nt][2] = fmaxf(acc1[mt][nt][2] + bb.x, 0.0f);
                acc1[mt][nt][3] = fmaxf(acc1[mt][nt][3] + bb.y, 0.0f);
            }
        }

        // ================= Layer 2: [32 x 64] @ [64 x 64] =================
        float acc2[2][8][4];
        #pragma unroll
        for (int mt = 0; mt < 2; mt++)
            #pragma unroll
            for (int nt = 0; nt < 8; nt++)
                #pragma unroll
                for (int q = 0; q < 4; q++) acc2[mt][nt][q] = 0.0f;

        #pragma unroll
        for (int kt = 0; kt < 4; kt++) {
            uint32_t ah[2][4], al[2][4];
            #pragma unroll
            for (int mt = 0; mt < 2; mt++) {
                const float* s0 = acc1[mt][2 * kt];
                const float* s1 = acc1[mt][2 * kt + 1];
                ah[mt][0] = pack_hi(s0[0], s0[1]);  al[mt][0] = pack_lo(s0[0], s0[1]);
                ah[mt][1] = pack_hi(s0[2], s0[3]);  al[mt][1] = pack_lo(s0[2], s0[3]);
                ah[mt][2] = pack_hi(s1[0], s1[1]);  al[mt][2] = pack_lo(s1[0], s1[1]);
                ah[mt][3] = pack_hi(s1[2], s1[3]);  al[mt][3] = pack_lo(s1[2], s1[3]);
            }
            #pragma unroll
            for (int nt = 0; nt < 8; nt++) {
                const int off = ((nt * 8 + r4) * 72 + kt * 16 + 2 * i4) * 2;
                uint32_t bh0 = *(const uint32_t*)(smem + OFF_W2HI + off);
                uint32_t bh1 = *(const uint32_t*)(smem + OFF_W2HI + off + 16);
                uint32_t bl0 = *(const uint32_t*)(smem + OFF_W2LO + off);
                uint32_t bl1 = *(const uint32_t*)(smem + OFF_W2LO + off + 16);
                #pragma unroll
                for (int mt = 0; mt < 2; mt++) {
                    mma_bf16(acc2[mt][nt], ah[mt], bh0, bh1);
                    mma_bf16(acc2[mt][nt], ah[mt], bl0, bl1);
                    mma_bf16(acc2[mt][nt], al[mt], bh0, bh1);
                }
            }
        }
        // epi2
        #pragma unroll
        for (int nt = 0; nt < 8; nt++) {
            float2 bb = *(const float2*)(b2s + nt * 8 + 2 * i4);
            #pragma unroll
            for (int mt = 0; mt < 2; mt++) {
                acc2[mt][nt][0] = fmaxf(acc2[mt][nt][0] + bb.x, 0.0f);
                acc2[mt][nt][1] = fmaxf(acc2[mt][nt][1] + bb.y, 0.0f);
                acc2[mt][nt][2] = fmaxf(acc2[mt][nt][2] + bb.x, 0.0f);
                acc2[mt][nt][3] = fmaxf(acc2[mt][nt][3] + bb.y, 0.0f);
            }
        }

        // ================= Layer 3: [32 x 64] @ [64 x 32] =================
        float acc3[2][4][4];
        #pragma unroll
        for (int mt = 0; mt < 2; mt++)
            #pragma unroll
            for (int nt = 0; nt < 4; nt++)
                #pragma unroll
                for (int q = 0; q < 4; q++) acc3[mt][nt][q] = 0.0f;

        #pragma unroll
        for (int kt = 0; kt < 4; kt++) {
            uint32_t ah[2][4], al[2][4];
            #pragma unroll
            for (int mt = 0; mt < 2; mt++) {
                const float* s0 = acc2[mt][2 * kt];
                const float* s1 = acc2[mt][2 * kt + 1];
                ah[mt][0] = pack_hi(s0[0], s0[1]);  al[mt][0] = pack_lo(s0[0], s0[1]);
                ah[mt][1] = pack_hi(s0[2], s0[3]);  al[mt][1] = pack_lo(s0[2], s0[3]);
                ah[mt][2] = pack_hi(s1[0], s1[1]);  al[mt][2] = pack_lo(s1[0], s1[1]);
                ah[mt][3] = pack_hi(s1[2], s1[3]);  al[mt][3] = pack_lo(s1[2], s1[3]);
            }
            #pragma unroll
            for (int nt = 0; nt < 4; nt++) {
                const int off = ((nt * 8 + r4) * 72 + kt * 16 + 2 * i4) * 2;
                uint32_t bh0 = *(const uint32_t*)(smem + OFF_W3HI + off);
                uint32_t bh1 = *(const uint32_t*)(smem + OFF_W3HI + off + 16);
                uint32_t bl0 = *(const uint32_t*)(smem + OFF_W3LO + off);
                uint32_t bl1 = *(const uint32_t*)(smem + OFF_W3LO + off + 16);
                #pragma unroll
                for (int mt = 0; mt < 2; mt++) {
                    mma_bf16(acc3[mt][nt], ah[mt], bh0, bh1);
                    mma_bf16(acc3[mt][nt], ah[mt], bl0, bl1);
                    mma_bf16(acc3[mt][nt], al[mt], bh0, bh1);
                }
            }
        }

        // epi3: bias, write to per-warp flush buffer [32][33]
        #pragma unroll
        for (int nt = 0; nt < 4; nt++) {
            float2 bb = *(const float2*)(b3s + nt * 8 + 2 * i4);
            #pragma unroll
            for (int mt = 0; mt < 2; mt++) {
                const int rA = mt * 16 + r4;
                const int cc = nt * 8 + 2 * i4;
                fbuf[rA * 33 + cc]           = acc3[mt][nt][0] + bb.x;
                fbuf[rA * 33 + cc + 1]       = acc3[mt][nt][1] + bb.y;
                fbuf[(rA + 8) * 33 + cc]     = acc3[mt][nt][2] + bb.x;
                fbuf[(rA + 8) * 33 + cc + 1] = acc3[mt][nt][3] + bb.y;
            }
        }
        __syncwarp();

        // run-length segment flush: lane owns column `lane`
        {
            int cur = -1;
            float a = 0.0f;
            #pragma unroll 4
            for (int i = 0; i < 32; i++) {
                int s = __shfl_sync(0xffffffffu, myseg, i);
                float v = fbuf[i * 33 + lane];
                if (s != cur) {
                    if (cur >= 0) atomicAdd(&out[cur * 32 + lane], a);
                    cur = s; a = v;
                } else {
                    a += v;
                }
            }
            if (cur >= 0) atomicAdd(&out[cur * 32 + lane], a);
        }
        __syncwarp();
    }
}

extern "C" void kernel_launch(void* const* d_in, const int* in_sizes, int n_in,
                              void* d_out, int out_size) {
    const float* x      = (const float*)d_in[0];
    const float* h_node = (const float*)d_in[1];
    const float* W1     = (const float*)d_in[2];
    const float* b1     = (const float*)d_in[3];
    const float* W2     = (const float*)d_in[4];
    const float* b2     = (const float*)d_in[5];
    const float* W3     = (const float*)d_in[6];
    const float* b3     = (const float*)d_in[7];
    const int*   ptr    = (const int*)d_in[8];
    float* out = (float*)d_out;

    const int N = in_sizes[1] / 32;     // h_node is [N, 32]
    const int M = in_sizes[8] - 1;      // ptr has M+1 entries
    const int numChunks = (N + CHUNK - 1) / CHUNK;

    zero_out_kernel<<<(out_size + 255) / 256, 256>>>(out, out_size);
    segfill_kernel<<<M, 64>>>(ptr, M);

    cudaFuncSetAttribute(dag_mma_kernel,
                         cudaFuncAttributeMaxDynamicSharedMemorySize, SMEM_BYTES);

    int dev = 0;
    cudaGetDevice(&dev);
    int sm_count = 148;
    cudaDeviceGetAttribute(&sm_count, cudaDevAttrMultiProcessorCount, dev);

    dag_mma_kernel<<<sm_count * 2, NT, SMEM_BYTES>>>(
        x, h_node, W1, b1, W2, b2, W3, b3, out, N, numChunks);
}

// round 5
// speedup vs baseline: 5.0070x; 1.0849x over previous
#include <cuda_runtime.h>
#include <cuda_bf16.h>
#include <cstdint>

#define NT 128
#define CHUNK 32

__device__ int g_seg[2000128];

#define OFF_W1HI 0
#define OFF_W1LO 7168
#define OFF_W2HI 14336
#define OFF_W2LO 23552
#define OFF_W3HI 32768
#define OFF_W3LO 37376
#define OFF_B1   41984
#define OFF_B2   42240
#define OFF_B3   42496
#define OFF_FLUSH 42624
#define SMEM_BYTES 59520

static __device__ __forceinline__ void mma_bf16(float c[4], const uint32_t a[4],
                                                uint32_t b0, uint32_t b1) {
    asm volatile(
        "mma.sync.aligned.m16n8k16.row.col.f32.bf16.bf16.f32 "
        "{%0,%1,%2,%3}, {%4,%5,%6,%7}, {%8,%9}, {%0,%1,%2,%3};"
        : "+f"(c[0]), "+f"(c[1]), "+f"(c[2]), "+f"(c[3])
        : "r"(a[0]), "r"(a[1]), "r"(a[2]), "r"(a[3]), "r"(b0), "r"(b1));
}

static __device__ __forceinline__ uint32_t pack_hi(float v0, float v1) {
    return __byte_perm(__float_as_uint(v0), __float_as_uint(v1), 0x7632);
}
static __device__ __forceinline__ uint32_t pack_lo(float v0, float v1) {
    float h0 = __uint_as_float(__float_as_uint(v0) & 0xFFFF0000u);
    float h1 = __uint_as_float(__float_as_uint(v1) & 0xFFFF0000u);
    __nv_bfloat162 p = __floats2bfloat162_rn(v0 - h0, v1 - h1);
    return *(uint32_t*)&p;
}

static __device__ __forceinline__ void mma3(float c[4], const uint32_t ah[4],
                                            const uint32_t al[4],
                                            uint32_t bh0, uint32_t bh1,
                                            uint32_t bl0, uint32_t bl1) {
    mma_bf16(c, ah, bh0, bh1);
    mma_bf16(c, ah, bl0, bl1);
    mma_bf16(c, al, bh0, bh1);
}

static __device__ __forceinline__ void repack(const float* s0, const float* s1,
                                              uint32_t ah[4], uint32_t al[4]) {
    ah[0] = pack_hi(s0[0], s0[1]);  al[0] = pack_lo(s0[0], s0[1]);
    ah[1] = pack_hi(s0[2], s0[3]);  al[1] = pack_lo(s0[2], s0[3]);
    ah[2] = pack_hi(s1[0], s1[1]);  al[2] = pack_lo(s1[0], s1[1]);
    ah[3] = pack_hi(s1[2], s1[3]);  al[3] = pack_lo(s1[2], s1[3]);
}

static __device__ __forceinline__ float2 load_in(const float* __restrict__ x,
                                                 const float* __restrict__ h,
                                                 int row, int kk, int N) {
    float2 v = make_float2(0.f, 0.f);
    if (row < N) {
        if (kk < 8)       v = *(const float2*)(x + (size_t)row * 8 + kk);
        else if (kk < 40) v = *(const float2*)(h + (size_t)row * 32 + (kk - 8));
    }
    return v;
}

// prefetch one chunk's inputs for this lane (24 float2)
static __device__ __forceinline__ void prefetch_chunk(const float* __restrict__ x,
                                                      const float* __restrict__ h,
                                                      int base, int N, int r4, int i4,
                                                      float2 pA[12], float2 pB[12]) {
    #pragma unroll
    for (int kt = 0; kt < 3; kt++)
        #pragma unroll
        for (int mt = 0; mt < 2; mt++)
            #pragma unroll
            for (int p = 0; p < 2; p++) {
                int idx = kt * 4 + mt * 2 + p;
                int rA = base + mt * 16 + r4;
                int kk = kt * 16 + 2 * i4 + 8 * p;
                pA[idx] = load_in(x, h, rA, kk, N);
                pB[idx] = load_in(x, h, rA + 8, kk, N);
            }
}

// merged init: zero output + fill g_seg
__global__ void init_kernel(const int* __restrict__ ptr, float* __restrict__ out,
                            int out_size, int M) {
    int tid = blockIdx.x * blockDim.x + threadIdx.x;
    int nth = gridDim.x * blockDim.x;
    for (int j = tid; j < out_size; j += nth) out[j] = 0.0f;
    int warp = tid >> 5, lane = tid & 31, nwarps = nth >> 5;
    for (int s = warp; s < M; s += nwarps) {
        int a = ptr[s], b = ptr[s + 1];
        for (int i = a + lane; i < b; i += 32) g_seg[i] = s;
    }
}

__global__ __launch_bounds__(NT, 2)
void dag_mma_kernel(
    const float* __restrict__ x, const float* __restrict__ h_node,
    const float* __restrict__ W1, const float* __restrict__ b1,
    const float* __restrict__ W2, const float* __restrict__ b2,
    const float* __restrict__ W3, const float* __restrict__ b3,
    float* __restrict__ out, int N, int numChunks)
{
    extern __shared__ char smem[];
    const int t = threadIdx.x;

    // ---- stage weights (same layout as R3: [n][k] bf16, hi=trunc, lo=residual) ----
    for (int i = t; i < 64 * 48; i += NT) {
        int n = i / 48, k = i % 48;
        float w = (k < 40) ? W1[k * 64 + n] : 0.0f;
        uint32_t u = __float_as_uint(w);
        *(uint16_t*)(smem + OFF_W1HI + (n * 56 + k) * 2) = (uint16_t)(u >> 16);
        *(__nv_bfloat16*)(smem + OFF_W1LO + (n * 56 + k) * 2) =
            __float2bfloat16(w - __uint_as_float(u & 0xFFFF0000u));
    }
    for (int i = t; i < 64 * 64; i += NT) {
        int n = i / 64, k = i % 64;
        float w = W2[k * 64 + n];
        uint32_t u = __float_as_uint(w);
        *(uint16_t*)(smem + OFF_W2HI + (n * 72 + k) * 2) = (uint16_t)(u >> 16);
        *(__nv_bfloat16*)(smem + OFF_W2LO + (n * 72 + k) * 2) =
            __float2bfloat16(w - __uint_as_float(u & 0xFFFF0000u));
    }
    for (int i = t; i < 32 * 64; i += NT) {
        int n = i / 64, k = i % 64;
        float w = W3[k * 32 + n];
        uint32_t u = __float_as_uint(w);
        *(uint16_t*)(smem + OFF_W3HI + (n * 72 + k) * 2) = (uint16_t)(u >> 16);
        *(__nv_bfloat16*)(smem + OFF_W3LO + (n * 72 + k) * 2) =
            __float2bfloat16(w - __uint_as_float(u & 0xFFFF0000u));
    }
    if (t < 64) {
        ((float*)(smem + OFF_B1))[t] = b1[t];
        ((float*)(smem + OFF_B2))[t] = b2[t];
    }
    if (t < 32) ((float*)(smem + OFF_B3))[t] = b3[t];
    __syncthreads();

    const float* b1s = (const float*)(smem + OFF_B1);
    const float* b2s = (const float*)(smem + OFF_B2);
    const float* b3s = (const float*)(smem + OFF_B3);

    const int lane = t & 31, wid = t >> 5;
    const int i4 = lane & 3, r4 = lane >> 2;
    float* fbuf = (float*)(smem + OFF_FLUSH) + wid * (32 * 33);

    const int warpsTotal = gridDim.x * (NT / 32);
    const int warpGlobal = blockIdx.x * (NT / 32) + wid;

    // ---- initial prefetch ----
    float2 pA[12], pB[12];
    int pseg = -1;
    if (warpGlobal < numChunks) {
        prefetch_chunk(x, h_node, warpGlobal * CHUNK, N, r4, i4, pA, pB);
        int node = warpGlobal * CHUNK + lane;
        if (node < N) pseg = g_seg[node];
    }

    for (int c = warpGlobal; c < numChunks; c += warpsTotal) {
        const int myseg = pseg;

        // ================= Layer 1 (A-frags from prefetch regs) =================
        float acc1[2][8][4];
        #pragma unroll
        for (int mt = 0; mt < 2; mt++)
            #pragma unroll
            for (int nt = 0; nt < 8; nt++)
                #pragma unroll
                for (int q = 0; q < 4; q++) acc1[mt][nt][q] = 0.0f;

        #pragma unroll
        for (int kt = 0; kt < 3; kt++) {
            uint32_t ah[2][4], al[2][4];
            #pragma unroll
            for (int mt = 0; mt < 2; mt++)
                #pragma unroll
                for (int p = 0; p < 2; p++) {
                    float2 fA = pA[kt * 4 + mt * 2 + p];
                    float2 fB = pB[kt * 4 + mt * 2 + p];
                    ah[mt][2 * p]     = pack_hi(fA.x, fA.y);
                    ah[mt][2 * p + 1] = pack_hi(fB.x, fB.y);
                    al[mt][2 * p]     = pack_lo(fA.x, fA.y);
                    al[mt][2 * p + 1] = pack_lo(fB.x, fB.y);
                }
            #pragma unroll
            for (int nt = 0; nt < 8; nt++) {
                const int off = ((nt * 8 + r4) * 56 + kt * 16 + 2 * i4) * 2;
                uint32_t bh0 = *(const uint32_t*)(smem + OFF_W1HI + off);
                uint32_t bh1 = *(const uint32_t*)(smem + OFF_W1HI + off + 16);
                uint32_t bl0 = *(const uint32_t*)(smem + OFF_W1LO + off);
                uint32_t bl1 = *(const uint32_t*)(smem + OFF_W1LO + off + 16);
                #pragma unroll
                for (int mt = 0; mt < 2; mt++)
                    mma3(acc1[mt][nt], ah[mt], al[mt], bh0, bh1, bl0, bl1);
            }
        }
        #pragma unroll
        for (int nt = 0; nt < 8; nt++) {
            float2 bb = *(const float2*)(b1s + nt * 8 + 2 * i4);
            #pragma unroll
            for (int mt = 0; mt < 2; mt++) {
                acc1[mt][nt][0] = fmaxf(acc1[mt][nt][0] + bb.x, 0.0f);
                acc1[mt][nt][1] = fmaxf(acc1[mt][nt][1] + bb.y, 0.0f);
                acc1[mt][nt][2] = fmaxf(acc1[mt][nt][2] + bb.x, 0.0f);
                acc1[mt][nt][3] = fmaxf(acc1[mt][nt][3] + bb.y, 0.0f);
            }
        }

        // ---- issue next-chunk prefetch; latency hides under L2+L3+flush ----
        {
            int cn = c + warpsTotal;
            if (cn < numChunks) {
                prefetch_chunk(x, h_node, cn * CHUNK, N, r4, i4, pA, pB);
                int node = cn * CHUNK + lane;
                pseg = (node < N) ? g_seg[node] : -1;
            }
        }

        // ================= Layer 2 =================
        float acc2[2][8][4];
        #pragma unroll
        for (int mt = 0; mt < 2; mt++)
            #pragma unroll
            for (int nt = 0; nt < 8; nt++)
                #pragma unroll
                for (int q = 0; q < 4; q++) acc2[mt][nt][q] = 0.0f;

        #pragma unroll
        for (int kt = 0; kt < 4; kt++) {
            uint32_t ah[2][4], al[2][4];
            #pragma unroll
            for (int mt = 0; mt < 2; mt++)
                repack(acc1[mt][2 * kt], acc1[mt][2 * kt + 1], ah[mt], al[mt]);
            #pragma unroll
            for (int nt = 0; nt < 8; nt++) {
                const int off = ((nt * 8 + r4) * 72 + kt * 16 + 2 * i4) * 2;
                uint32_t bh0 = *(const uint32_t*)(smem + OFF_W2HI + off);
                uint32_t bh1 = *(const uint32_t*)(smem + OFF_W2HI + off + 16);
                uint32_t bl0 = *(const uint32_t*)(smem + OFF_W2LO + off);
                uint32_t bl1 = *(const uint32_t*)(smem + OFF_W2LO + off + 16);
                #pragma unroll
                for (int mt = 0; mt < 2; mt++)
                    mma3(acc2[mt][nt], ah[mt], al[mt], bh0, bh1, bl0, bl1);
            }
        }
        #pragma unroll
        for (int nt = 0; nt < 8; nt++) {
            float2 bb = *(const float2*)(b2s + nt * 8 + 2 * i4);
            #pragma unroll
            for (int mt = 0; mt < 2; mt++) {
                acc2[mt][nt][0] = fmaxf(acc2[mt][nt][0] + bb.x, 0.0f);
                acc2[mt][nt][1] = fmaxf(acc2[mt][nt][1] + bb.y, 0.0f);
                acc2[mt][nt][2] = fmaxf(acc2[mt][nt][2] + bb.x, 0.0f);
                acc2[mt][nt][3] = fmaxf(acc2[mt][nt][3] + bb.y, 0.0f);
            }
        }

        // ================= Layer 3 =================
        float acc3[2][4][4];
        #pragma unroll
        for (int mt = 0; mt < 2; mt++)
            #pragma unroll
            for (int nt = 0; nt < 4; nt++)
                #pragma unroll
                for (int q = 0; q < 4; q++) acc3[mt][nt][q] = 0.0f;

        #pragma unroll
        for (int kt = 0; kt < 4; kt++) {
            uint32_t ah[2][4], al[2][4];
            #pragma unroll
            for (int mt = 0; mt < 2; mt++)
                repack(acc2[mt][2 * kt], acc2[mt][2 * kt + 1], ah[mt], al[mt]);
            #pragma unroll
            for (int nt = 0; nt < 4; nt++) {
                const int off = ((nt * 8 + r4) * 72 + kt * 16 + 2 * i4) * 2;
                uint32_t bh0 = *(const uint32_t*)(smem + OFF_W3HI + off);
                uint32_t bh1 = *(const uint32_t*)(smem + OFF_W3HI + off + 16);
                uint32_t bl0 = *(const uint32_t*)(smem + OFF_W3LO + off);
                uint32_t bl1 = *(const uint32_t*)(smem + OFF_W3LO + off + 16);
                #pragma unroll
                for (int mt = 0; mt < 2; mt++)
                    mma3(acc3[mt][nt], ah[mt], al[mt], bh0, bh1, bl0, bl1);
            }
        }

        // epi3: bias -> per-warp flush buffer [32][33]
        #pragma unroll
        for (int nt = 0; nt < 4; nt++) {
            float2 bb = *(const float2*)(b3s + nt * 8 + 2 * i4);
            #pragma unroll
            for (int mt = 0; mt < 2; mt++) {
                const int rA = mt * 16 + r4;
                const int cc = nt * 8 + 2 * i4;
                fbuf[rA * 33 + cc]           = acc3[mt][nt][0] + bb.x;
                fbuf[rA * 33 + cc + 1]       = acc3[mt][nt][1] + bb.y;
                fbuf[(rA + 8) * 33 + cc]     = acc3[mt][nt][2] + bb.x;
                fbuf[(rA + 8) * 33 + cc + 1] = acc3[mt][nt][3] + bb.y;
            }
        }
        __syncwarp();

        // run-length segment flush
        {
            int cur = -1;
            float a = 0.0f;
            #pragma unroll 4
            for (int i = 0; i < 32; i++) {
                int s = __shfl_sync(0xffffffffu, myseg, i);
                float v = fbuf[i * 33 + lane];
                if (s != cur) {
                    if (cur >= 0) atomicAdd(&out[cur * 32 + lane], a);
                    cur = s; a = v;
                } else {
                    a += v;
                }
            }
            if (cur >= 0) atomicAdd(&out[cur * 32 + lane], a);
        }
        __syncwarp();
    }
}

extern "C" void kernel_launch(void* const* d_in, const int* in_sizes, int n_in,
                              void* d_out, int out_size) {
    const float* x      = (const float*)d_in[0];
    const float* h_node = (const float*)d_in[1];
    const float* W1     = (const float*)d_in[2];
    const float* b1     = (const float*)d_in[3];
    const float* W2     = (const float*)d_in[4];
    const float* b2     = (const float*)d_in[5];
    const float* W3     = (const float*)d_in[6];
    const float* b3     = (const float*)d_in[7];
    const int*   ptr    = (const int*)d_in[8];
    float* out = (float*)d_out;

    const int N = in_sizes[1] / 32;
    const int M = in_sizes[8] - 1;
    const int numChunks = (N + CHUNK - 1) / CHUNK;

    init_kernel<<<592, 256>>>(ptr, out, out_size, M);

    cudaFuncSetAttribute(dag_mma_kernel,
                         cudaFuncAttributeMaxDynamicSharedMemorySize, SMEM_BYTES);

    int dev = 0;
    cudaGetDevice(&dev);
    int sm_count = 148;
    cudaDeviceGetAttribute(&sm_count, cudaDevAttrMultiProcessorCount, dev);

    dag_mma_kernel<<<sm_count * 2, NT, SMEM_BYTES>>>(
        x, h_node, W1, b1, W2, b2, W3, b3, out, N, numChunks);
}

// round 6
// speedup vs baseline: 5.2726x; 1.0530x over previous
#include <cuda_runtime.h>
#include <cuda_bf16.h>
#include <cstdint>

#define NT 128
#define CHUNK 16

__device__ int g_seg[2000128];

// weight quads: entry (n,kt,i4) = 8B {pack(k0,k0+1), pack(k0+8,k0+9)}, row stride 40 words
#define OFF_W1HI 0
#define OFF_W1LO 10240
#define OFF_W2HI 20480
#define OFF_W2LO 30720
#define OFF_W3HI 40960
#define OFF_W3LO 46080
#define OFF_B1   51200
#define OFF_B2   51456
#define OFF_B3   51712
#define OFF_FLUSH 51840   // 4 warps * 16*33 f32 = 8448
#define SMEM_BYTES 60288

static __device__ __forceinline__ void mma_bf16(float c[4], const uint32_t a[4],
                                                uint32_t b0, uint32_t b1) {
    asm volatile(
        "mma.sync.aligned.m16n8k16.row.col.f32.bf16.bf16.f32 "
        "{%0,%1,%2,%3}, {%4,%5,%6,%7}, {%8,%9}, {%0,%1,%2,%3};"
        : "+f"(c[0]), "+f"(c[1]), "+f"(c[2]), "+f"(c[3])
        : "r"(a[0]), "r"(a[1]), "r"(a[2]), "r"(a[3]), "r"(b0), "r"(b1));
}
static __device__ __forceinline__ uint32_t pack_hi(float v0, float v1) {
    return __byte_perm(__float_as_uint(v0), __float_as_uint(v1), 0x7632);
}
static __device__ __forceinline__ uint32_t pack_lo(float v0, float v1) {
    float h0 = __uint_as_float(__float_as_uint(v0) & 0xFFFF0000u);
    float h1 = __uint_as_float(__float_as_uint(v1) & 0xFFFF0000u);
    __nv_bfloat162 p = __floats2bfloat162_rn(v0 - h0, v1 - h1);
    return *(uint32_t*)&p;
}
static __device__ __forceinline__ void mma3(float c[4], const uint32_t ah[4],
                                            const uint32_t al[4], uint2 bh, uint2 bl) {
    mma_bf16(c, ah, bh.x, bh.y);
    mma_bf16(c, ah, bl.x, bl.y);
    mma_bf16(c, al, bh.x, bh.y);
}
static __device__ __forceinline__ void repack(const float* s0, const float* s1,
                                              uint32_t ah[4], uint32_t al[4]) {
    ah[0] = pack_hi(s0[0], s0[1]);  al[0] = pack_lo(s0[0], s0[1]);
    ah[1] = pack_hi(s0[2], s0[3]);  al[1] = pack_lo(s0[2], s0[3]);
    ah[2] = pack_hi(s1[0], s1[1]);  al[2] = pack_lo(s1[0], s1[1]);
    ah[3] = pack_hi(s1[2], s1[3]);  al[3] = pack_lo(s1[2], s1[3]);
}
static __device__ __forceinline__ float2 load_in(const float* __restrict__ x,
                                                 const float* __restrict__ h,
                                                 int row, int kk, int N) {
    float2 v = make_float2(0.f, 0.f);
    if (row < N) {
        if (kk < 8)       v = *(const float2*)(x + (size_t)row * 8 + kk);
        else if (kk < 40) v = *(const float2*)(h + (size_t)row * 32 + (kk - 8));
    }
    return v;
}
static __device__ __forceinline__ void prefetch_chunk(const float* __restrict__ x,
                                                      const float* __restrict__ h,
                                                      int base, int N, int r4, int i4,
                                                      float2 pA[6], float2 pB[6]) {
    #pragma unroll
    for (int kt = 0; kt < 3; kt++)
        #pragma unroll
        for (int p = 0; p < 2; p++) {
            int kk = kt * 16 + 2 * i4 + 8 * p;
            pA[kt * 2 + p] = load_in(x, h, base + r4, kk, N);
            pB[kt * 2 + p] = load_in(x, h, base + 8 + r4, kk, N);
        }
}

__global__ void init_kernel(const int* __restrict__ ptr, float* __restrict__ out,
                            int out_size, int M) {
    int tid = blockIdx.x * blockDim.x + threadIdx.x;
    int nth = gridDim.x * blockDim.x;
    for (int j = tid; j < out_size; j += nth) out[j] = 0.0f;
    int warp = tid >> 5, lane = tid & 31, nwarps = nth >> 5;
    for (int s = warp; s < M; s += nwarps) {
        int a = ptr[s], b = ptr[s + 1];
        for (int i = a + lane; i < b; i += 32) g_seg[i] = s;
    }
}

// stage one weight matrix as interleaved hi/lo quads
static __device__ __forceinline__ void stage_w(char* smem, int offH, int offL,
                                               const float* __restrict__ W,
                                               int nrows, int nkt, int kmax, int ncols,
                                               int t) {
    int entries = nrows * nkt * 4;
    for (int e = t; e < entries; e += NT) {
        int n = e / (nkt * 4), r = e % (nkt * 4), kt = r >> 2, i4 = r & 3;
        int k0 = kt * 16 + 2 * i4;
        float w0 = (k0     < kmax) ? W[(k0)     * ncols + n] : 0.f;
        float w1 = (k0 + 1 < kmax) ? W[(k0 + 1) * ncols + n] : 0.f;
        float w2 = (k0 + 8 < kmax) ? W[(k0 + 8) * ncols + n] : 0.f;
        float w3 = (k0 + 9 < kmax) ? W[(k0 + 9) * ncols + n] : 0.f;
        int off = (n * 40 + kt * 8 + i4 * 2) * 4;
        *(uint2*)(smem + offH + off) = make_uint2(pack_hi(w0, w1), pack_hi(w2, w3));
        *(uint2*)(smem + offL + off) = make_uint2(pack_lo(w0, w1), pack_lo(w2, w3));
    }
}

__global__ __launch_bounds__(NT, 3)
void dag_mma_kernel(
    const float* __restrict__ x, const float* __restrict__ h_node,
    const float* __restrict__ W1, const float* __restrict__ b1,
    const float* __restrict__ W2, const float* __restrict__ b2,
    const float* __restrict__ W3, const float* __restrict__ b3,
    float* __restrict__ out, int N, int numChunks)
{
    extern __shared__ char smem[];
    const int t = threadIdx.x;

    stage_w(smem, OFF_W1HI, OFF_W1LO, W1, 64, 3, 40, 64, t);
    stage_w(smem, OFF_W2HI, OFF_W2LO, W2, 64, 4, 64, 64, t);
    stage_w(smem, OFF_W3HI, OFF_W3LO, W3, 32, 4, 64, 32, t);
    if (t < 64) {
        ((float*)(smem + OFF_B1))[t] = b1[t];
        ((float*)(smem + OFF_B2))[t] = b2[t];
    }
    if (t < 32) ((float*)(smem + OFF_B3))[t] = b3[t];
    __syncthreads();

    const float* b1s = (const float*)(smem + OFF_B1);
    const float* b2s = (const float*)(smem + OFF_B2);
    const float* b3s = (const float*)(smem + OFF_B3);

    const int lane = t & 31, wid = t >> 5;
    const int i4 = lane & 3, r4 = lane >> 2;
    float* fbuf = (float*)(smem + OFF_FLUSH) + wid * (16 * 33);

    const int warpsTotal = gridDim.x * (NT / 32);
    const int warpGlobal = blockIdx.x * (NT / 32) + wid;

    float2 pA[6], pB[6];
    int pseg = -1;
    if (warpGlobal < numChunks) {
        prefetch_chunk(x, h_node, warpGlobal * CHUNK, N, r4, i4, pA, pB);
        int node = warpGlobal * CHUNK + lane;
        if (lane < CHUNK && node < N) pseg = g_seg[node];
    }

    for (int c = warpGlobal; c < numChunks; c += warpsTotal) {
        const int myseg = pseg;

        // ---------- Layer 1: [16 x 48] @ [48 x 64] ----------
        float acc1[8][4];
        #pragma unroll
        for (int nt = 0; nt < 8; nt++)
            #pragma unroll
            for (int q = 0; q < 4; q++) acc1[nt][q] = 0.0f;

        #pragma unroll
        for (int kt = 0; kt < 3; kt++) {
            uint32_t ah[4], al[4];
            #pragma unroll
            for (int p = 0; p < 2; p++) {
                float2 fA = pA[kt * 2 + p], fB = pB[kt * 2 + p];
                ah[2 * p]     = pack_hi(fA.x, fA.y);
                ah[2 * p + 1] = pack_hi(fB.x, fB.y);
                al[2 * p]     = pack_lo(fA.x, fA.y);
                al[2 * p + 1] = pack_lo(fB.x, fB.y);
            }
            #pragma unroll
            for (int nt = 0; nt < 8; nt++) {
                const int off = ((nt * 8 + r4) * 40 + kt * 8 + i4 * 2) * 4;
                uint2 bh = *(const uint2*)(smem + OFF_W1HI + off);
                uint2 bl = *(const uint2*)(smem + OFF_W1LO + off);
                mma3(acc1[nt], ah, al, bh, bl);
            }
        }
        #pragma unroll
        for (int nt = 0; nt < 8; nt++) {
            float2 bb = *(const float2*)(b1s + nt * 8 + 2 * i4);
            acc1[nt][0] = fmaxf(acc1[nt][0] + bb.x, 0.0f);
            acc1[nt][1] = fmaxf(acc1[nt][1] + bb.y, 0.0f);
            acc1[nt][2] = fmaxf(acc1[nt][2] + bb.x, 0.0f);
            acc1[nt][3] = fmaxf(acc1[nt][3] + bb.y, 0.0f);
        }

        // ---- prefetch next chunk (hides under L2+L3+flush) ----
        {
            int cn = c + warpsTotal;
            if (cn < numChunks) {
                prefetch_chunk(x, h_node, cn * CHUNK, N, r4, i4, pA, pB);
                int node = cn * CHUNK + lane;
                pseg = (lane < CHUNK && node < N) ? g_seg[node] : -1;
            }
        }

        // ---------- Layer 2: [16 x 64] @ [64 x 64] ----------
        float acc2[8][4];
        #pragma unroll
        for (int nt = 0; nt < 8; nt++)
            #pragma unroll
            for (int q = 0; q < 4; q++) acc2[nt][q] = 0.0f;

        #pragma unroll
        for (int kt = 0; kt < 4; kt++) {
            uint32_t ah[4], al[4];
            repack(acc1[2 * kt], acc1[2 * kt + 1], ah, al);
            #pragma unroll
            for (int nt = 0; nt < 8; nt++) {
                const int off = ((nt * 8 + r4) * 40 + kt * 8 + i4 * 2) * 4;
                uint2 bh = *(const uint2*)(smem + OFF_W2HI + off);
                uint2 bl = *(const uint2*)(smem + OFF_W2LO + off);
                mma3(acc2[nt], ah, al, bh, bl);
            }
        }
        #pragma unroll
        for (int nt = 0; nt < 8; nt++) {
            float2 bb = *(const float2*)(b2s + nt * 8 + 2 * i4);
            acc2[nt][0] = fmaxf(acc2[nt][0] + bb.x, 0.0f);
            acc2[nt][1] = fmaxf(acc2[nt][1] + bb.y, 0.0f);
            acc2[nt][2] = fmaxf(acc2[nt][2] + bb.x, 0.0f);
            acc2[nt][3] = fmaxf(acc2[nt][3] + bb.y, 0.0f);
        }

        // ---------- Layer 3: [16 x 64] @ [64 x 32] ----------
        float acc3[4][4];
        #pragma unroll
        for (int nt = 0; nt < 4; nt++)
            #pragma unroll
            for (int q = 0; q < 4; q++) acc3[nt][q] = 0.0f;

        #pragma unroll
        for (int kt = 0; kt < 4; kt++) {
            uint32_t ah[4], al[4];
            repack(acc2[2 * kt], acc2[2 * kt + 1], ah, al);
            #pragma unroll
            for (int nt = 0; nt < 4; nt++) {
                const int off = ((nt * 8 + r4) * 40 + kt * 8 + i4 * 2) * 4;
                uint2 bh = *(const uint2*)(smem + OFF_W3HI + off);
                uint2 bl = *(const uint2*)(smem + OFF_W3LO + off);
                mma3(acc3[nt], ah, al, bh, bl);
            }
        }

        // epi3: bias -> per-warp flush buffer [16][33]
        #pragma unroll
        for (int nt = 0; nt < 4; nt++) {
            float2 bb = *(const float2*)(b3s + nt * 8 + 2 * i4);
            const int cc = nt * 8 + 2 * i4;
            fbuf[r4 * 33 + cc]           = acc3[nt][0] + bb.x;
            fbuf[r4 * 33 + cc + 1]       = acc3[nt][1] + bb.y;
            fbuf[(r4 + 8) * 33 + cc]     = acc3[nt][2] + bb.x;
            fbuf[(r4 + 8) * 33 + cc + 1] = acc3[nt][3] + bb.y;
        }
        __syncwarp();

        // run-length segment flush: lane owns output column `lane`
        {
            int cur = -1;
            float a = 0.0f;
            #pragma unroll 4
            for (int i = 0; i < CHUNK; i++) {
                int s = __shfl_sync(0xffffffffu, myseg, i);
                float v = fbuf[i * 33 + lane];
                if (s != cur) {
                    if (cur >= 0) atomicAdd(&out[cur * 32 + lane], a);
                    cur = s; a = v;
                } else {
                    a += v;
                }
            }
            if (cur >= 0) atomicAdd(&out[cur * 32 + lane], a);
        }
        __syncwarp();
    }
}

extern "C" void kernel_launch(void* const* d_in, const int* in_sizes, int n_in,
                              void* d_out, int out_size) {
    const float* x      = (const float*)d_in[0];
    const float* h_node = (const float*)d_in[1];
    const float* W1     = (const float*)d_in[2];
    const float* b1     = (const float*)d_in[3];
    const float* W2     = (const float*)d_in[4];
    const float* b2     = (const float*)d_in[5];
    const float* W3     = (const float*)d_in[6];
    const float* b3     = (const float*)d_in[7];
    const int*   ptr    = (const int*)d_in[8];
    float* out = (float*)d_out;

    const int N = in_sizes[1] / 32;
    const int M = in_sizes[8] - 1;
    const int numChunks = (N + CHUNK - 1) / CHUNK;

    init_kernel<<<592, 256>>>(ptr, out, out_size, M);

    cudaFuncSetAttribute(dag_mma_kernel,
                         cudaFuncAttributeMaxDynamicSharedMemorySize, SMEM_BYTES);

    int dev = 0;
    cudaGetDevice(&dev);
    int sm_count = 148;
    cudaDeviceGetAttribute(&sm_count, cudaDevAttrMultiProcessorCount, dev);

    dag_mma_kernel<<<sm_count * 3, NT, SMEM_BYTES>>>(
        x, h_node, W1, b1, W2, b2, W3, b3, out, N, numChunks);
}

// round 7
// speedup vs baseline: 5.2836x; 1.0021x over previous
#include <cuda_runtime.h>
#include <cuda_bf16.h>
#include <cstdint>

#define NT 128
#define CHUNK 16

__device__ int g_seg[2000128];

// fused weight quads: entry (n,kt,i4) = 16B {bh0,bh1,bl0,bl1}; row stride 320B
#define OFF_W1   0        // 64 n * 320B = 20480
#define OFF_W2   20480    // 64 n * 320B
#define OFF_W3   40960    // 32 n * 320B = 10240
#define OFF_B1   51200
#define OFF_B2   51456
#define OFF_B3   51712
#define OFF_FLUSH 51840   // 4 warps * 16*33 f32 = 8448
#define SMEM_BYTES 60288

static __device__ __forceinline__ void mma_bf16(float c[4], const uint32_t a[4],
                                                uint32_t b0, uint32_t b1) {
    asm volatile(
        "mma.sync.aligned.m16n8k16.row.col.f32.bf16.bf16.f32 "
        "{%0,%1,%2,%3}, {%4,%5,%6,%7}, {%8,%9}, {%0,%1,%2,%3};"
        : "+f"(c[0]), "+f"(c[1]), "+f"(c[2]), "+f"(c[3])
        : "r"(a[0]), "r"(a[1]), "r"(a[2]), "r"(a[3]), "r"(b0), "r"(b1));
}
static __device__ __forceinline__ uint32_t pack_hi(float v0, float v1) {
    return __byte_perm(__float_as_uint(v0), __float_as_uint(v1), 0x7632);
}
static __device__ __forceinline__ uint32_t pack_lo(float v0, float v1) {
    float h0 = __uint_as_float(__float_as_uint(v0) & 0xFFFF0000u);
    float h1 = __uint_as_float(__float_as_uint(v1) & 0xFFFF0000u);
    __nv_bfloat162 p = __floats2bfloat162_rn(v0 - h0, v1 - h1);
    return *(uint32_t*)&p;
}
// 3-pass split MMA: hi*hi + hi*lo + lo*hi
static __device__ __forceinline__ void mma3(float c[4], const uint32_t ah[4],
                                            const uint32_t al[4], uint4 q) {
    mma_bf16(c, ah, q.x, q.y);
    mma_bf16(c, ah, q.z, q.w);
    mma_bf16(c, al, q.x, q.y);
}
static __device__ __forceinline__ void repack(const float* s0, const float* s1,
                                              uint32_t ah[4], uint32_t al[4]) {
    ah[0] = pack_hi(s0[0], s0[1]);  al[0] = pack_lo(s0[0], s0[1]);
    ah[1] = pack_hi(s0[2], s0[3]);  al[1] = pack_lo(s0[2], s0[3]);
    ah[2] = pack_hi(s1[0], s1[1]);  al[2] = pack_lo(s1[0], s1[1]);
    ah[3] = pack_hi(s1[2], s1[3]);  al[3] = pack_lo(s1[2], s1[3]);
}
static __device__ __forceinline__ float2 load_in(const float* __restrict__ x,
                                                 const float* __restrict__ h,
                                                 int row, int kk, int N) {
    float2 v = make_float2(0.f, 0.f);
    if (row < N) {
        if (kk < 8)       v = *(const float2*)(x + (size_t)row * 8 + kk);
        else if (kk < 40) v = *(const float2*)(h + (size_t)row * 32 + (kk - 8));
    }
    return v;
}
static __device__ __forceinline__ void prefetch_chunk(const float* __restrict__ x,
                                                      const float* __restrict__ h,
                                                      int base, int N, int r4, int i4,
                                                      float2 pA[6], float2 pB[6]) {
    #pragma unroll
    for (int kt = 0; kt < 3; kt++)
        #pragma unroll
        for (int p = 0; p < 2; p++) {
            int kk = kt * 16 + 2 * i4 + 8 * p;
            pA[kt * 2 + p] = load_in(x, h, base + r4, kk, N);
            pB[kt * 2 + p] = load_in(x, h, base + 8 + r4, kk, N);
        }
}

__global__ void init_kernel(const int* __restrict__ ptr, float* __restrict__ out,
                            int out_size, int M) {
    int tid = blockIdx.x * blockDim.x + threadIdx.x;
    int nth = gridDim.x * blockDim.x;
    for (int j = tid; j < out_size; j += nth) out[j] = 0.0f;
    int warp = tid >> 5, lane = tid & 31, nwarps = nth >> 5;
    for (int s = warp; s < M; s += nwarps) {
        int a = ptr[s], b = ptr[s + 1];
        for (int i = a + lane; i < b; i += 32) g_seg[i] = s;
    }
}

// stage one weight matrix as fused 16B hi/lo quads
static __device__ __forceinline__ void stage_w(char* smem, int offW,
                                               const float* __restrict__ W,
                                               int nrows, int nkt, int kmax, int ncols,
                                               int t) {
    int entries = nrows * nkt * 4;
    for (int e = t; e < entries; e += NT) {
        int n = e / (nkt * 4), r = e % (nkt * 4), kt = r >> 2, i4 = r & 3;
        int k0 = kt * 16 + 2 * i4;
        float w0 = (k0     < kmax) ? W[(k0)     * ncols + n] : 0.f;
        float w1 = (k0 + 1 < kmax) ? W[(k0 + 1) * ncols + n] : 0.f;
        float w2 = (k0 + 8 < kmax) ? W[(k0 + 8) * ncols + n] : 0.f;
        float w3 = (k0 + 9 < kmax) ? W[(k0 + 9) * ncols + n] : 0.f;
        int off = (n * 20 + kt * 4 + i4) * 16;
        *(uint4*)(smem + offW + off) =
            make_uint4(pack_hi(w0, w1), pack_hi(w2, w3), pack_lo(w0, w1), pack_lo(w2, w3));
    }
}

__global__ __launch_bounds__(NT, 3)
void dag_mma_kernel(
    const float* __restrict__ x, const float* __restrict__ h_node,
    const float* __restrict__ W1, const float* __restrict__ b1,
    const float* __restrict__ W2, const float* __restrict__ b2,
    const float* __restrict__ W3, const float* __restrict__ b3,
    float* __restrict__ out, int N, int numChunks)
{
    extern __shared__ char smem[];
    const int t = threadIdx.x;

    stage_w(smem, OFF_W1, W1, 64, 3, 40, 64, t);
    stage_w(smem, OFF_W2, W2, 64, 4, 64, 64, t);
    stage_w(smem, OFF_W3, W3, 32, 4, 64, 32, t);
    if (t < 64) {
        ((float*)(smem + OFF_B1))[t] = b1[t];
        ((float*)(smem + OFF_B2))[t] = b2[t];
    }
    if (t < 32) ((float*)(smem + OFF_B3))[t] = b3[t];
    __syncthreads();

    const float* b1s = (const float*)(smem + OFF_B1);
    const float* b2s = (const float*)(smem + OFF_B2);
    const float* b3s = (const float*)(smem + OFF_B3);

    const int lane = t & 31, wid = t >> 5;
    const int i4 = lane & 3, r4 = lane >> 2;
    // per-thread base inside a weight row-block: r4*320 + i4*16 bytes
    const char* wbase = smem + (r4 * 320 + i4 * 16);
    float* fbuf = (float*)(smem + OFF_FLUSH) + wid * (16 * 33);

    const int warpsTotal = gridDim.x * (NT / 32);
    const int warpGlobal = blockIdx.x * (NT / 32) + wid;

    float2 pA[6], pB[6];
    int pseg = -1;
    if (warpGlobal < numChunks) {
        prefetch_chunk(x, h_node, warpGlobal * CHUNK, N, r4, i4, pA, pB);
        int node = warpGlobal * CHUNK + lane;
        if (lane < CHUNK && node < N) pseg = g_seg[node];
    }

    for (int c = warpGlobal; c < numChunks; c += warpsTotal) {
        const int myseg = pseg;

        // ---------- Layer 1: [16 x 48] @ [48 x 64] ----------
        float acc1[8][4];
        #pragma unroll
        for (int nt = 0; nt < 8; nt++)
            #pragma unroll
            for (int q = 0; q < 4; q++) acc1[nt][q] = 0.0f;

        #pragma unroll
        for (int kt = 0; kt < 3; kt++) {
            uint32_t ah[4], al[4];
            #pragma unroll
            for (int p = 0; p < 2; p++) {
                float2 fA = pA[kt * 2 + p], fB = pB[kt * 2 + p];
                ah[2 * p]     = pack_hi(fA.x, fA.y);
                ah[2 * p + 1] = pack_hi(fB.x, fB.y);
                al[2 * p]     = pack_lo(fA.x, fA.y);
                al[2 * p + 1] = pack_lo(fB.x, fB.y);
            }
            #pragma unroll
            for (int nt = 0; nt < 8; nt++) {
                uint4 q = *(const uint4*)(wbase + OFF_W1 + nt * 2560 + kt * 64);
                mma3(acc1[nt], ah, al, q);
            }
        }
        #pragma unroll
        for (int nt = 0; nt < 8; nt++) {
            float2 bb = *(const float2*)(b1s + nt * 8 + 2 * i4);
            acc1[nt][0] = fmaxf(acc1[nt][0] + bb.x, 0.0f);
            acc1[nt][1] = fmaxf(acc1[nt][1] + bb.y, 0.0f);
            acc1[nt][2] = fmaxf(acc1[nt][2] + bb.x, 0.0f);
            acc1[nt][3] = fmaxf(acc1[nt][3] + bb.y, 0.0f);
        }

        // ---- prefetch next chunk (hides under L2+L3+flush) ----
        {
            int cn = c + warpsTotal;
            if (cn < numChunks) {
                prefetch_chunk(x, h_node, cn * CHUNK, N, r4, i4, pA, pB);
                int node = cn * CHUNK + lane;
                pseg = (lane < CHUNK && node < N) ? g_seg[node] : -1;
            }
        }

        // ---------- Layer 2: [16 x 64] @ [64 x 64] ----------
        float acc2[8][4];
        #pragma unroll
        for (int nt = 0; nt < 8; nt++)
            #pragma unroll
            for (int q = 0; q < 4; q++) acc2[nt][q] = 0.0f;

        #pragma unroll
        for (int kt = 0; kt < 4; kt++) {
            uint32_t ah[4], al[4];
            repack(acc1[2 * kt], acc1[2 * kt + 1], ah, al);
            #pragma unroll
            for (int nt = 0; nt < 8; nt++) {
                uint4 q = *(const uint4*)(wbase + OFF_W2 + nt * 2560 + kt * 64);
                mma3(acc2[nt], ah, al, q);
            }
        }
        #pragma unroll
        for (int nt = 0; nt < 8; nt++) {
            float2 bb = *(const float2*)(b2s + nt * 8 + 2 * i4);
            acc2[nt][0] = fmaxf(acc2[nt][0] + bb.x, 0.0f);
            acc2[nt][1] = fmaxf(acc2[nt][1] + bb.y, 0.0f);
            acc2[nt][2] = fmaxf(acc2[nt][2] + bb.x, 0.0f);
            acc2[nt][3] = fmaxf(acc2[nt][3] + bb.y, 0.0f);
        }

        // ---------- Layer 3: [16 x 64] @ [64 x 32] ----------
        float acc3[4][4];
        #pragma unroll
        for (int nt = 0; nt < 4; nt++)
            #pragma unroll
            for (int q = 0; q < 4; q++) acc3[nt][q] = 0.0f;

        #pragma unroll
        for (int kt = 0; kt < 4; kt++) {
            uint32_t ah[4], al[4];
            repack(acc2[2 * kt], acc2[2 * kt + 1], ah, al);
            #pragma unroll
            for (int nt = 0; nt < 4; nt++) {
                uint4 q = *(const uint4*)(wbase + OFF_W3 + nt * 2560 + kt * 64);
                mma3(acc3[nt], ah, al, q);
            }
        }

        // epi3: bias -> per-warp flush buffer [16][33]
        #pragma unroll
        for (int nt = 0; nt < 4; nt++) {
            float2 bb = *(const float2*)(b3s + nt * 8 + 2 * i4);
            const int cc = nt * 8 + 2 * i4;
            fbuf[r4 * 33 + cc]           = acc3[nt][0] + bb.x;
            fbuf[r4 * 33 + cc + 1]       = acc3[nt][1] + bb.y;
            fbuf[(r4 + 8) * 33 + cc]     = acc3[nt][2] + bb.x;
            fbuf[(r4 + 8) * 33 + cc + 1] = acc3[nt][3] + bb.y;
        }
        __syncwarp();

        // run-length segment flush: lane owns output column `lane`
        {
            int cur = -1;
            float a = 0.0f;
            #pragma unroll 4
            for (int i = 0; i < CHUNK; i++) {
                int s = __shfl_sync(0xffffffffu, myseg, i);
                float v = fbuf[i * 33 + lane];
                if (s != cur) {
                    if (cur >= 0) atomicAdd(&out[cur * 32 + lane], a);
                    cur = s; a = v;
                } else {
                    a += v;
                }
            }
            if (cur >= 0) atomicAdd(&out[cur * 32 + lane], a);
        }
        __syncwarp();
    }
}

extern "C" void kernel_launch(void* const* d_in, const int* in_sizes, int n_in,
                              void* d_out, int out_size) {
    const float* x      = (const float*)d_in[0];
    const float* h_node = (const float*)d_in[1];
    const float* W1     = (const float*)d_in[2];
    const float* b1     = (const float*)d_in[3];
    const float* W2     = (const float*)d_in[4];
    const float* b2     = (const float*)d_in[5];
    const float* W3     = (const float*)d_in[6];
    const float* b3     = (const float*)d_in[7];
    const int*   ptr    = (const int*)d_in[8];
    float* out = (float*)d_out;

    const int N = in_sizes[1] / 32;
    const int M = in_sizes[8] - 1;
    const int numChunks = (N + CHUNK - 1) / CHUNK;

    init_kernel<<<592, 256>>>(ptr, out, out_size, M);

    cudaFuncSetAttribute(dag_mma_kernel,
                         cudaFuncAttributeMaxDynamicSharedMemorySize, SMEM_BYTES);

    int dev = 0;
    cudaGetDevice(&dev);
    int sm_count = 148;
    cudaDeviceGetAttribute(&sm_count, cudaDevAttrMultiProcessorCount, dev);

    dag_mma_kernel<<<sm_count * 3, NT, SMEM_BYTES>>>(
        x, h_node, W1, b1, W2, b2, W3, b3, out, N, numChunks);
}